// round 11
// baseline (speedup 1.0000x reference)
#include <cuda_runtime.h>

#define NE   50000
#define NRL  64
#define NT   400000
#define D    128
#define NH   8
#define NBLK 196   // ceil(NE/256)

// ---------------- scratch (device globals; no allocation) ----------------
__device__ float g_P1[NE * D];      // emb_ent @ Wa[0:128] + ba   (tail part)
__device__ float g_P2[NE * D];      // emb_ent @ Wa[128:256]      (head part)
__device__ float g_G1[NE * D];      // emb_ent @ Wg[0:128] + bg   (msg head part)
__device__ float g_Ra[NRL * D];     // emb_rel @ Wa[256:384]
__device__ float g_Rg[NRL * D];     // emb_rel @ Wg[128:256]
__device__ int   g_off[NE + 1];
__device__ int   g_cur[NE];
__device__ int   g_deg[NE];
__device__ int   g_part[256];
__device__ int2  g_ehr[NT];         // CSR payload: (head, rel), grouped by tail

// ---------------- helpers ----------------
__device__ __forceinline__ float tanh_fast(float x) {
    float y;
    asm("tanh.approx.f32 %0, %1;" : "=f"(y) : "f"(x));
    return y;
}
__device__ __forceinline__ unsigned long long dup2(float x) {
    unsigned long long r;
    asm("mov.b64 %0, {%1, %1};" : "=l"(r) : "f"(x));
    return r;
}
__device__ __forceinline__ unsigned long long ffma2(unsigned long long a,
                                                    unsigned long long b,
                                                    unsigned long long c) {
    unsigned long long d;
    asm("fma.rn.f32x2 %0, %1, %2, %3;" : "=l"(d) : "l"(a), "l"(b), "l"(c));
    return d;
}

// ---------------- K0: zero deg + cursors ----------------
__global__ void k_zero() {
    int i = blockIdx.x * blockDim.x + threadIdx.x;
    if (i < NE) { g_deg[i] = 0; g_cur[i] = 0; }
}

// ---------------- K1: degree count ----------------
__global__ void k_count(const int* __restrict__ trip) {
    int i = blockIdx.x * blockDim.x + threadIdx.x;
    if (i < NT) atomicAdd(&g_deg[trip[i * 3 + 2]], 1);
}

// ---------------- K2: Ra, Rg (64 x 128 each) ----------------
__global__ void k_rel(const float* __restrict__ emb_rel,
                      const float* __restrict__ Wa,
                      const float* __restrict__ Wg) {
    __shared__ float x[D];
    int r = blockIdx.x;
    int j = threadIdx.x;
    x[j] = emb_rel[r * D + j];
    __syncthreads();
    float ra = 0.0f, rg = 0.0f;
    #pragma unroll 8
    for (int k = 0; k < D; k++) {
        float xv = x[k];
        ra = fmaf(xv, Wa[(256 + k) * D + j], ra);
        rg = fmaf(xv, Wg[(128 + k) * D + j], rg);
    }
    g_Ra[r * D + j] = ra;
    g_Rg[r * D + j] = rg;
}

// ---------------- K3: per-entity GEMM via packed fma.rn.f32x2 ----------------
__global__ __launch_bounds__(256, 2) void k_ent(const float* __restrict__ X,
                                                const float* __restrict__ Wa,
                                                const float* __restrict__ Wg,
                                                const float* __restrict__ ba,
                                                const float* __restrict__ bg) {
    extern __shared__ float sm[];
    float (*Xs)[16][256] = (float(*)[16][256])sm;            // [buf][k][2*m dup]
    float (*Ws)[16][128] = (float(*)[16][128])(sm + 8192);   // [buf][k][j]

    int tid = threadIdx.x;
    int tx = tid & 15;
    int ty = tid >> 4;
    int m_base = blockIdx.x * 128;
    int w = blockIdx.y;

    const float* Wp = (w == 0) ? Wa : (w == 1) ? (Wa + 128 * D) : Wg;
    float* C = (w == 0) ? g_P1 : (w == 1) ? g_P2 : g_G1;

    int lm  = tid >> 1;
    int lk4 = (tid & 1) * 8;
    int gm_ld = m_base + lm;
    int wr_r  = tid >> 5;
    int wc4   = (tid & 31) * 4;

    unsigned long long acc[2][2][4][2];
    #pragma unroll
    for (int a = 0; a < 2; a++)
        #pragma unroll
        for (int b = 0; b < 2; b++)
            #pragma unroll
            for (int i = 0; i < 4; i++) {
                acc[a][b][i][0] = 0ULL;
                acc[a][b][i][1] = 0ULL;
            }

    float4 xv0, xv1, wv0, wv1;
    {
        xv0 = make_float4(0, 0, 0, 0); xv1 = make_float4(0, 0, 0, 0);
        if (gm_ld < NE) {
            xv0 = *(const float4*)&X[gm_ld * D + lk4];
            xv1 = *(const float4*)&X[gm_ld * D + lk4 + 4];
        }
        wv0 = *(const float4*)&Wp[wr_r * D + wc4];
        wv1 = *(const float4*)&Wp[(wr_r + 8) * D + wc4];
        *(unsigned long long*)&Xs[0][lk4 + 0][2 * lm] = dup2(xv0.x);
        *(unsigned long long*)&Xs[0][lk4 + 1][2 * lm] = dup2(xv0.y);
        *(unsigned long long*)&Xs[0][lk4 + 2][2 * lm] = dup2(xv0.z);
        *(unsigned long long*)&Xs[0][lk4 + 3][2 * lm] = dup2(xv0.w);
        *(unsigned long long*)&Xs[0][lk4 + 4][2 * lm] = dup2(xv1.x);
        *(unsigned long long*)&Xs[0][lk4 + 5][2 * lm] = dup2(xv1.y);
        *(unsigned long long*)&Xs[0][lk4 + 6][2 * lm] = dup2(xv1.z);
        *(unsigned long long*)&Xs[0][lk4 + 7][2 * lm] = dup2(xv1.w);
        *(float4*)&Ws[0][wr_r][wc4]     = wv0;
        *(float4*)&Ws[0][wr_r + 8][wc4] = wv1;
    }
    __syncthreads();

    #pragma unroll
    for (int it = 0; it < 8; ++it) {
        int buf = it & 1;
        if (it < 7) {
            int kb = (it + 1) * 16;
            xv0 = make_float4(0, 0, 0, 0); xv1 = make_float4(0, 0, 0, 0);
            if (gm_ld < NE) {
                xv0 = *(const float4*)&X[gm_ld * D + kb + lk4];
                xv1 = *(const float4*)&X[gm_ld * D + kb + lk4 + 4];
            }
            wv0 = *(const float4*)&Wp[(kb + wr_r) * D + wc4];
            wv1 = *(const float4*)&Wp[(kb + wr_r + 8) * D + wc4];
        }
        #pragma unroll
        for (int kk = 0; kk < 16; ++kk) {
            const ulonglong2* xr = (const ulonglong2*)&Xs[buf][kk][0];
            ulonglong2 xa0 = xr[2 * ty];
            ulonglong2 xa1 = xr[2 * ty + 1];
            ulonglong2 xb0 = xr[32 + 2 * ty];
            ulonglong2 xb1 = xr[32 + 2 * ty + 1];
            ulonglong2 wA = *(const ulonglong2*)&Ws[buf][kk][tx * 4];
            ulonglong2 wB = *(const ulonglong2*)&Ws[buf][kk][64 + tx * 4];

            unsigned long long xd[2][4] = {
                { xa0.x, xa0.y, xa1.x, xa1.y },
                { xb0.x, xb0.y, xb1.x, xb1.y }
            };
            #pragma unroll
            for (int a = 0; a < 2; a++)
                #pragma unroll
                for (int i = 0; i < 4; i++) {
                    acc[a][0][i][0] = ffma2(xd[a][i], wA.x, acc[a][0][i][0]);
                    acc[a][0][i][1] = ffma2(xd[a][i], wA.y, acc[a][0][i][1]);
                    acc[a][1][i][0] = ffma2(xd[a][i], wB.x, acc[a][1][i][0]);
                    acc[a][1][i][1] = ffma2(xd[a][i], wB.y, acc[a][1][i][1]);
                }
        }
        if (it < 7) {
            int nb = buf ^ 1;
            *(unsigned long long*)&Xs[nb][lk4 + 0][2 * lm] = dup2(xv0.x);
            *(unsigned long long*)&Xs[nb][lk4 + 1][2 * lm] = dup2(xv0.y);
            *(unsigned long long*)&Xs[nb][lk4 + 2][2 * lm] = dup2(xv0.z);
            *(unsigned long long*)&Xs[nb][lk4 + 3][2 * lm] = dup2(xv0.w);
            *(unsigned long long*)&Xs[nb][lk4 + 4][2 * lm] = dup2(xv1.x);
            *(unsigned long long*)&Xs[nb][lk4 + 5][2 * lm] = dup2(xv1.y);
            *(unsigned long long*)&Xs[nb][lk4 + 6][2 * lm] = dup2(xv1.z);
            *(unsigned long long*)&Xs[nb][lk4 + 7][2 * lm] = dup2(xv1.w);
            *(float4*)&Ws[nb][wr_r][wc4]     = wv0;
            *(float4*)&Ws[nb][wr_r + 8][wc4] = wv1;
        }
        __syncthreads();
    }

    #pragma unroll
    for (int a = 0; a < 2; a++)
        #pragma unroll
        for (int i = 0; i < 4; i++) {
            int gm = m_base + a * 64 + ty * 4 + i;
            if (gm < NE) {
                #pragma unroll
                for (int b = 0; b < 2; b++) {
                    int col = b * 64 + tx * 4;
                    float4 bias = make_float4(0, 0, 0, 0);
                    if (w == 0) bias = *(const float4*)&ba[col];
                    else if (w == 2) bias = *(const float4*)&bg[col];
                    uint2 lo = *reinterpret_cast<uint2*>(&acc[a][b][i][0]);
                    uint2 hi = *reinterpret_cast<uint2*>(&acc[a][b][i][1]);
                    float4 v = make_float4(__uint_as_float(lo.x) + bias.x,
                                           __uint_as_float(lo.y) + bias.y,
                                           __uint_as_float(hi.x) + bias.z,
                                           __uint_as_float(hi.y) + bias.w);
                    *(float4*)&C[gm * D + col] = v;
                }
            }
        }
}

// ---------------- K4a/b/c: decoupled 3-phase exclusive scan of degrees -----
__global__ void k_scanA() {
    __shared__ int s[256];
    int t = threadIdx.x;
    int i = blockIdx.x * 256 + t;
    s[t] = (i < NE) ? g_deg[i] : 0;
    __syncthreads();
    #pragma unroll
    for (int o = 128; o > 0; o >>= 1) {
        if (t < o) s[t] += s[t + o];
        __syncthreads();
    }
    if (t == 0) g_part[blockIdx.x] = s[0];
}
__global__ void k_scanB() {
    __shared__ int s[256];
    int t = threadIdx.x;
    int v = (t < NBLK) ? g_part[t] : 0;
    s[t] = v;
    __syncthreads();
    #pragma unroll
    for (int o = 1; o < 256; o <<= 1) {
        int u = (t >= o) ? s[t - o] : 0;
        __syncthreads();
        s[t] += u;
        __syncthreads();
    }
    if (t < NBLK) g_part[t] = s[t] - v;          // exclusive
    if (t == NBLK - 1) g_off[NE] = s[t];
}
__global__ void k_scanC() {
    __shared__ int s[256];
    int t = threadIdx.x;
    int i = blockIdx.x * 256 + t;
    int v = (i < NE) ? g_deg[i] : 0;
    s[t] = v;
    __syncthreads();
    #pragma unroll
    for (int o = 1; o < 256; o <<= 1) {
        int u = (t >= o) ? s[t - o] : 0;
        __syncthreads();
        s[t] += u;
        __syncthreads();
    }
    if (i < NE) g_off[i] = g_part[blockIdx.x] + s[t] - v;
}

// ---------------- K5: scatter (head, rel) into CSR ----------------
__global__ void k_scatter(const int* __restrict__ trip) {
    int i = blockIdx.x * blockDim.x + threadIdx.x;
    if (i < NT) {
        int hd = trip[i * 3 + 0];
        int rl = trip[i * 3 + 1];
        int tl = trip[i * 3 + 2];
        int p = atomicAdd(&g_cur[tl], 1);
        g_ehr[g_off[tl] + p] = make_int2(hd, rl);
    }
}

// ---------------- K6: fused attention + softmax + aggregation -------------
// TWO warps per entity: each walks alternate edges (halved serial chain,
// doubled warp pool vs R5). Odd warp dumps 13 per-lane partials to smem;
// after __syncthreads the even warp merges (exact fp32 adds), handles the
// self edge, writes out. No max-subtraction (softmax shift-invariant).
__global__ __launch_bounds__(256) void k_gather(const float* __restrict__ av,
                                                float* __restrict__ out) {
    __shared__ float sbuf[4][13][32];   // [pair][field][lane]

    int tid  = threadIdx.x;
    int warp = tid >> 5;
    int lane = tid & 31;
    int pair = warp >> 1;
    int half = warp & 1;
    int e = blockIdx.x * 4 + pair;

    int o0 = 0, deg = 0;
    float4 p1;
    int j = lane * 4;
    float4 av4 = *(const float4*)&av[j];
    if (e < NE) {
        o0 = g_off[e];
        deg = g_off[e + 1] - o0;
        p1 = *(const float4*)&g_P1[e * D + j];   // includes ba
    }

    float ax = 0.f, ay = 0.f, az = 0.f, aw = 0.f;
    float denom = 0.f;
    float sax = 0.f, say = 0.f, saz = 0.f, saw = 0.f;  // sum Ra[rel]
    float sgx = 0.f, sgy = 0.f, sgz = 0.f, sgw = 0.f;  // sum Rg[rel]

    if (e < NE) {
        float4 p2c, rac, g1c, rgc;
        int jj = half;
        if (jj < deg) {
            int2 hr = g_ehr[o0 + jj];
            p2c = *(const float4*)&g_P2[hr.x * D + j];
            rac = *(const float4*)&g_Ra[hr.y * D + j];
            g1c = *(const float4*)&g_G1[hr.x * D + j];
            rgc = *(const float4*)&g_Rg[hr.y * D + j];
        }
        for (; jj < deg; jj += 2) {
            float4 p2n, ran, g1n, rgn;
            if (jj + 2 < deg) {
                int2 hr = g_ehr[o0 + jj + 2];
                p2n = *(const float4*)&g_P2[hr.x * D + j];
                ran = *(const float4*)&g_Ra[hr.y * D + j];
                g1n = *(const float4*)&g_G1[hr.x * D + j];
                rgn = *(const float4*)&g_Rg[hr.y * D + j];
            }
            float s = 0.f;
            s = fmaf(tanh_fast(p1.x + p2c.x + rac.x), av4.x, s);
            s = fmaf(tanh_fast(p1.y + p2c.y + rac.y), av4.y, s);
            s = fmaf(tanh_fast(p1.z + p2c.z + rac.z), av4.z, s);
            s = fmaf(tanh_fast(p1.w + p2c.w + rac.w), av4.w, s);
            s += __shfl_xor_sync(0xffffffffu, s, 1);
            s += __shfl_xor_sync(0xffffffffu, s, 2);
            float ev = __expf(s);

            ax = fmaf(ev, g1c.x + rgc.x, ax);   // g1 includes bg
            ay = fmaf(ev, g1c.y + rgc.y, ay);
            az = fmaf(ev, g1c.z + rgc.z, az);
            aw = fmaf(ev, g1c.w + rgc.w, aw);
            denom += ev;

            sax += rac.x; say += rac.y; saz += rac.z; saw += rac.w;
            sgx += rgc.x; sgy += rgc.y; sgz += rgc.z; sgw += rgc.w;

            p2c = p2n; rac = ran; g1c = g1n; rgc = rgn;
        }
    }

    // odd warp publishes partials
    if (half == 1) {
        sbuf[pair][0][lane] = ax;  sbuf[pair][1][lane] = ay;
        sbuf[pair][2][lane] = az;  sbuf[pair][3][lane] = aw;
        sbuf[pair][4][lane] = denom;
        sbuf[pair][5][lane] = sax; sbuf[pair][6][lane] = say;
        sbuf[pair][7][lane] = saz; sbuf[pair][8][lane] = saw;
        sbuf[pair][9][lane] = sgx; sbuf[pair][10][lane] = sgy;
        sbuf[pair][11][lane] = sgz; sbuf[pair][12][lane] = sgw;
    }
    __syncthreads();

    if (half == 0 && e < NE) {
        ax += sbuf[pair][0][lane];  ay += sbuf[pair][1][lane];
        az += sbuf[pair][2][lane];  aw += sbuf[pair][3][lane];
        denom += sbuf[pair][4][lane];
        sax += sbuf[pair][5][lane]; say += sbuf[pair][6][lane];
        saz += sbuf[pair][7][lane]; saw += sbuf[pair][8][lane];
        sgx += sbuf[pair][9][lane]; sgy += sbuf[pair][10][lane];
        sgz += sbuf[pair][11][lane]; sgw += sbuf[pair][12][lane];

        // ---- self edge: head = e, rel-feat = mean of Ra/Rg over in-edges
        float inv = (deg > 0) ? (1.0f / (float)deg) : 0.0f;
        float4 p2 = *(const float4*)&g_P2[e * D + j];
        float4 g1 = *(const float4*)&g_G1[e * D + j];
        float s = 0.f;
        s = fmaf(tanh_fast(p1.x + p2.x + sax * inv), av4.x, s);
        s = fmaf(tanh_fast(p1.y + p2.y + say * inv), av4.y, s);
        s = fmaf(tanh_fast(p1.z + p2.z + saz * inv), av4.z, s);
        s = fmaf(tanh_fast(p1.w + p2.w + saw * inv), av4.w, s);
        s += __shfl_xor_sync(0xffffffffu, s, 1);
        s += __shfl_xor_sync(0xffffffffu, s, 2);
        float ev = __expf(s);
        ax = fmaf(ev, g1.x + sgx * inv, ax);
        ay = fmaf(ev, g1.y + sgy * inv, ay);
        az = fmaf(ev, g1.z + sgz * inv, az);
        aw = fmaf(ev, g1.w + sgw * inv, aw);
        denom += ev;

        float dinv = 1.0f / denom;
        *(float4*)&out[e * D + j] = make_float4(ax * dinv, ay * dinv, az * dinv, aw * dinv);
    }
}

// ---------------- launch: fork CSR build + rel GEMV onto side stream -------
extern "C" void kernel_launch(void* const* d_in, const int* in_sizes, int n_in,
                              void* d_out, int out_size) {
    const float* emb_ent = (const float*)d_in[0];
    const float* emb_rel = (const float*)d_in[1];
    const int*   trip    = (const int*)d_in[2];
    const float* Wa      = (const float*)d_in[3];
    const float* ba      = (const float*)d_in[4];
    const float* av      = (const float*)d_in[5];
    const float* Wg      = (const float*)d_in[6];
    const float* bg      = (const float*)d_in[7];
    float* out = (float*)d_out;

    static cudaStream_t s2 = nullptr;
    static cudaEvent_t evF = nullptr, evJ = nullptr;
    if (s2 == nullptr) {
        cudaStreamCreateWithFlags(&s2, cudaStreamNonBlocking);
        cudaEventCreateWithFlags(&evF, cudaEventDisableTiming);
        cudaEventCreateWithFlags(&evJ, cudaEventDisableTiming);
        cudaFuncSetAttribute(k_ent, cudaFuncAttributeMaxDynamicSharedMemorySize, 49152);
    }

    // fork: CSR build + rel GEMV on side stream (~35us total, hidden by k_ent)
    cudaEventRecord(evF, 0);
    cudaStreamWaitEvent(s2, evF, 0);
    k_rel<<<NRL, 128, 0, s2>>>(emb_rel, Wa, Wg);
    k_zero<<<(NE + 255) / 256, 256, 0, s2>>>();
    k_count<<<(NT + 255) / 256, 256, 0, s2>>>(trip);
    k_scanA<<<NBLK, 256, 0, s2>>>();
    k_scanB<<<1, 256, 0, s2>>>();
    k_scanC<<<NBLK, 256, 0, s2>>>();
    k_scatter<<<(NT + 255) / 256, 256, 0, s2>>>(trip);
    cudaEventRecord(evJ, s2);

    // main stream: entity GEMM
    dim3 ent_grid((NE + 127) / 128, 3);
    k_ent<<<ent_grid, 256, 49152>>>(emb_ent, Wa, Wg, ba, bg);

    // join, then fused gather (2 warps/entity, 4 entities per 256-thread block)
    cudaStreamWaitEvent(0, evJ, 0);
    k_gather<<<(NE + 3) / 4, 256>>>(av, out);
}

// round 13
// speedup vs baseline: 1.1991x; 1.1991x over previous
#include <cuda_runtime.h>

#define NE   50000
#define NRL  64
#define NT   400000
#define D    128
#define NH   8
#define NBLK 196   // ceil(NE/256)

// ---------------- scratch (device globals; no allocation) ----------------
__device__ float g_P1[NE * D];      // emb_ent @ Wa[0:128] + ba   (tail part)
__device__ float g_P2[NE * D];      // emb_ent @ Wa[128:256]      (head part)
__device__ float g_G1[NE * D];      // emb_ent @ Wg[0:128] + bg   (msg head part)
__device__ float g_Ra[NRL * D];     // emb_rel @ Wa[256:384]
__device__ float g_Rg[NRL * D];     // emb_rel @ Wg[128:256]
__device__ int   g_off[NE + 1];
__device__ int   g_cur[NE];
__device__ int   g_deg[NE];
__device__ int   g_part[256];
__device__ int2  g_ehr[NT];         // CSR payload: (head, rel), grouped by tail

// ---------------- helpers ----------------
__device__ __forceinline__ float tanh_fast(float x) {
    float y;
    asm("tanh.approx.f32 %0, %1;" : "=f"(y) : "f"(x));
    return y;
}
__device__ __forceinline__ unsigned long long dup2(float x) {
    unsigned long long r;
    asm("mov.b64 %0, {%1, %1};" : "=l"(r) : "f"(x));
    return r;
}
__device__ __forceinline__ unsigned long long ffma2(unsigned long long a,
                                                    unsigned long long b,
                                                    unsigned long long c) {
    unsigned long long d;
    asm("fma.rn.f32x2 %0, %1, %2, %3;" : "=l"(d) : "l"(a), "l"(b), "l"(c));
    return d;
}

// ---------------- K0: zero deg + cursors ----------------
__global__ void k_zero() {
    int i = blockIdx.x * blockDim.x + threadIdx.x;
    if (i < NE) { g_deg[i] = 0; g_cur[i] = 0; }
}

// ---------------- K1: degree count ----------------
__global__ void k_count(const int* __restrict__ trip) {
    int i = blockIdx.x * blockDim.x + threadIdx.x;
    if (i < NT) atomicAdd(&g_deg[trip[i * 3 + 2]], 1);
}

// ---------------- K2: Ra, Rg (64 x 128 each) ----------------
__global__ void k_rel(const float* __restrict__ emb_rel,
                      const float* __restrict__ Wa,
                      const float* __restrict__ Wg) {
    __shared__ float x[D];
    int r = blockIdx.x;
    int j = threadIdx.x;
    x[j] = emb_rel[r * D + j];
    __syncthreads();
    float ra = 0.0f, rg = 0.0f;
    #pragma unroll 8
    for (int k = 0; k < D; k++) {
        float xv = x[k];
        ra = fmaf(xv, Wa[(256 + k) * D + j], ra);
        rg = fmaf(xv, Wg[(128 + k) * D + j], rg);
    }
    g_Ra[r * D + j] = ra;
    g_Rg[r * D + j] = rg;
}

// ---------------- K3: per-entity GEMM via packed fma.rn.f32x2 ----------------
// C(50000x128) = X @ W; blockIdx.y picks weight matrix (+ bias fold).
// X stored PRE-DUPLICATED in smem so LDS delivers ready f32x2 operands.
// Double-buffered, one barrier per K-step. 48KB dynamic smem.
__global__ __launch_bounds__(256, 2) void k_ent(const float* __restrict__ X,
                                                const float* __restrict__ Wa,
                                                const float* __restrict__ Wg,
                                                const float* __restrict__ ba,
                                                const float* __restrict__ bg) {
    extern __shared__ float sm[];
    float (*Xs)[16][256] = (float(*)[16][256])sm;            // [buf][k][2*m dup]
    float (*Ws)[16][128] = (float(*)[16][128])(sm + 8192);   // [buf][k][j]

    int tid = threadIdx.x;
    int tx = tid & 15;
    int ty = tid >> 4;
    int m_base = blockIdx.x * 128;
    int w = blockIdx.y;

    const float* Wp = (w == 0) ? Wa : (w == 1) ? (Wa + 128 * D) : Wg;
    float* C = (w == 0) ? g_P1 : (w == 1) ? g_P2 : g_G1;

    int lm  = tid >> 1;
    int lk4 = (tid & 1) * 8;
    int gm_ld = m_base + lm;
    int wr_r  = tid >> 5;
    int wc4   = (tid & 31) * 4;

    unsigned long long acc[2][2][4][2];
    #pragma unroll
    for (int a = 0; a < 2; a++)
        #pragma unroll
        for (int b = 0; b < 2; b++)
            #pragma unroll
            for (int i = 0; i < 4; i++) {
                acc[a][b][i][0] = 0ULL;
                acc[a][b][i][1] = 0ULL;
            }

    float4 xv0, xv1, wv0, wv1;
    {
        xv0 = make_float4(0, 0, 0, 0); xv1 = make_float4(0, 0, 0, 0);
        if (gm_ld < NE) {
            xv0 = *(const float4*)&X[gm_ld * D + lk4];
            xv1 = *(const float4*)&X[gm_ld * D + lk4 + 4];
        }
        wv0 = *(const float4*)&Wp[wr_r * D + wc4];
        wv1 = *(const float4*)&Wp[(wr_r + 8) * D + wc4];
        *(unsigned long long*)&Xs[0][lk4 + 0][2 * lm] = dup2(xv0.x);
        *(unsigned long long*)&Xs[0][lk4 + 1][2 * lm] = dup2(xv0.y);
        *(unsigned long long*)&Xs[0][lk4 + 2][2 * lm] = dup2(xv0.z);
        *(unsigned long long*)&Xs[0][lk4 + 3][2 * lm] = dup2(xv0.w);
        *(unsigned long long*)&Xs[0][lk4 + 4][2 * lm] = dup2(xv1.x);
        *(unsigned long long*)&Xs[0][lk4 + 5][2 * lm] = dup2(xv1.y);
        *(unsigned long long*)&Xs[0][lk4 + 6][2 * lm] = dup2(xv1.z);
        *(unsigned long long*)&Xs[0][lk4 + 7][2 * lm] = dup2(xv1.w);
        *(float4*)&Ws[0][wr_r][wc4]     = wv0;
        *(float4*)&Ws[0][wr_r + 8][wc4] = wv1;
    }
    __syncthreads();

    #pragma unroll
    for (int it = 0; it < 8; ++it) {
        int buf = it & 1;
        if (it < 7) {
            int kb = (it + 1) * 16;
            xv0 = make_float4(0, 0, 0, 0); xv1 = make_float4(0, 0, 0, 0);
            if (gm_ld < NE) {
                xv0 = *(const float4*)&X[gm_ld * D + kb + lk4];
                xv1 = *(const float4*)&X[gm_ld * D + kb + lk4 + 4];
            }
            wv0 = *(const float4*)&Wp[(kb + wr_r) * D + wc4];
            wv1 = *(const float4*)&Wp[(kb + wr_r + 8) * D + wc4];
        }
        #pragma unroll
        for (int kk = 0; kk < 16; ++kk) {
            const ulonglong2* xr = (const ulonglong2*)&Xs[buf][kk][0];
            ulonglong2 xa0 = xr[2 * ty];
            ulonglong2 xa1 = xr[2 * ty + 1];
            ulonglong2 xb0 = xr[32 + 2 * ty];
            ulonglong2 xb1 = xr[32 + 2 * ty + 1];
            ulonglong2 wA = *(const ulonglong2*)&Ws[buf][kk][tx * 4];
            ulonglong2 wB = *(const ulonglong2*)&Ws[buf][kk][64 + tx * 4];

            unsigned long long xd[2][4] = {
                { xa0.x, xa0.y, xa1.x, xa1.y },
                { xb0.x, xb0.y, xb1.x, xb1.y }
            };
            #pragma unroll
            for (int a = 0; a < 2; a++)
                #pragma unroll
                for (int i = 0; i < 4; i++) {
                    acc[a][0][i][0] = ffma2(xd[a][i], wA.x, acc[a][0][i][0]);
                    acc[a][0][i][1] = ffma2(xd[a][i], wA.y, acc[a][0][i][1]);
                    acc[a][1][i][0] = ffma2(xd[a][i], wB.x, acc[a][1][i][0]);
                    acc[a][1][i][1] = ffma2(xd[a][i], wB.y, acc[a][1][i][1]);
                }
        }
        if (it < 7) {
            int nb = buf ^ 1;
            *(unsigned long long*)&Xs[nb][lk4 + 0][2 * lm] = dup2(xv0.x);
            *(unsigned long long*)&Xs[nb][lk4 + 1][2 * lm] = dup2(xv0.y);
            *(unsigned long long*)&Xs[nb][lk4 + 2][2 * lm] = dup2(xv0.z);
            *(unsigned long long*)&Xs[nb][lk4 + 3][2 * lm] = dup2(xv0.w);
            *(unsigned long long*)&Xs[nb][lk4 + 4][2 * lm] = dup2(xv1.x);
            *(unsigned long long*)&Xs[nb][lk4 + 5][2 * lm] = dup2(xv1.y);
            *(unsigned long long*)&Xs[nb][lk4 + 6][2 * lm] = dup2(xv1.z);
            *(unsigned long long*)&Xs[nb][lk4 + 7][2 * lm] = dup2(xv1.w);
            *(float4*)&Ws[nb][wr_r][wc4]     = wv0;
            *(float4*)&Ws[nb][wr_r + 8][wc4] = wv1;
        }
        __syncthreads();
    }

    #pragma unroll
    for (int a = 0; a < 2; a++)
        #pragma unroll
        for (int i = 0; i < 4; i++) {
            int gm = m_base + a * 64 + ty * 4 + i;
            if (gm < NE) {
                #pragma unroll
                for (int b = 0; b < 2; b++) {
                    int col = b * 64 + tx * 4;
                    float4 bias = make_float4(0, 0, 0, 0);
                    if (w == 0) bias = *(const float4*)&ba[col];
                    else if (w == 2) bias = *(const float4*)&bg[col];
                    uint2 lo = *reinterpret_cast<uint2*>(&acc[a][b][i][0]);
                    uint2 hi = *reinterpret_cast<uint2*>(&acc[a][b][i][1]);
                    float4 v = make_float4(__uint_as_float(lo.x) + bias.x,
                                           __uint_as_float(lo.y) + bias.y,
                                           __uint_as_float(hi.x) + bias.z,
                                           __uint_as_float(hi.y) + bias.w);
                    *(float4*)&C[gm * D + col] = v;
                }
            }
        }
}

// ---------------- K4a/b/c: decoupled 3-phase exclusive scan of degrees -----
__global__ void k_scanA() {
    __shared__ int s[256];
    int t = threadIdx.x;
    int i = blockIdx.x * 256 + t;
    s[t] = (i < NE) ? g_deg[i] : 0;
    __syncthreads();
    #pragma unroll
    for (int o = 128; o > 0; o >>= 1) {
        if (t < o) s[t] += s[t + o];
        __syncthreads();
    }
    if (t == 0) g_part[blockIdx.x] = s[0];
}
__global__ void k_scanB() {
    __shared__ int s[256];
    int t = threadIdx.x;
    int v = (t < NBLK) ? g_part[t] : 0;
    s[t] = v;
    __syncthreads();
    #pragma unroll
    for (int o = 1; o < 256; o <<= 1) {
        int u = (t >= o) ? s[t - o] : 0;
        __syncthreads();
        s[t] += u;
        __syncthreads();
    }
    if (t < NBLK) g_part[t] = s[t] - v;          // exclusive
    if (t == NBLK - 1) g_off[NE] = s[t];
}
__global__ void k_scanC() {
    __shared__ int s[256];
    int t = threadIdx.x;
    int i = blockIdx.x * 256 + t;
    int v = (i < NE) ? g_deg[i] : 0;
    s[t] = v;
    __syncthreads();
    #pragma unroll
    for (int o = 1; o < 256; o <<= 1) {
        int u = (t >= o) ? s[t - o] : 0;
        __syncthreads();
        s[t] += u;
        __syncthreads();
    }
    if (i < NE) g_off[i] = g_part[blockIdx.x] + s[t] - v;
}

// ---------------- K5: scatter (head, rel) into CSR ----------------
__global__ void k_scatter(const int* __restrict__ trip) {
    int i = blockIdx.x * blockDim.x + threadIdx.x;
    if (i < NT) {
        int hd = trip[i * 3 + 0];
        int rl = trip[i * 3 + 1];
        int tl = trip[i * 3 + 2];
        int p = atomicAdd(&g_cur[tl], 1);
        g_ehr[g_off[tl] + p] = make_int2(hd, rl);
    }
}

// ---------------- K6: fused attention + softmax + aggregation -------------
// R5-proven version: 1 warp per entity, depth-1 software pipeline.
// ba folded into P1, bg folded into G1 (exact). No max-subtraction:
// |attn_raw| <= sum|av| ~ 1.5, exp safe, softmax shift-invariant.
__global__ __launch_bounds__(256) void k_gather(const float* __restrict__ av,
                                                float* __restrict__ out) {
    int e = (blockIdx.x * blockDim.x + threadIdx.x) >> 5;
    int lane = threadIdx.x & 31;
    if (e >= NE) return;
    int o0 = g_off[e];
    int deg = g_off[e + 1] - o0;

    int j = lane * 4;
    float4 p1  = *(const float4*)&g_P1[e * D + j];   // includes ba
    float4 av4 = *(const float4*)&av[j];

    float ax = 0.f, ay = 0.f, az = 0.f, aw = 0.f;
    float denom = 0.f;
    float sax = 0.f, say = 0.f, saz = 0.f, saw = 0.f;  // sum Ra[rel]
    float sgx = 0.f, sgy = 0.f, sgz = 0.f, sgw = 0.f;  // sum Rg[rel]

    float4 p2c, rac, g1c, rgc;
    if (deg > 0) {
        int2 hr = g_ehr[o0];
        p2c = *(const float4*)&g_P2[hr.x * D + j];
        rac = *(const float4*)&g_Ra[hr.y * D + j];
        g1c = *(const float4*)&g_G1[hr.x * D + j];
        rgc = *(const float4*)&g_Rg[hr.y * D + j];
    }
    for (int jj = 0; jj < deg; ++jj) {
        float4 p2n, ran, g1n, rgn;
        if (jj + 1 < deg) {
            int2 hr = g_ehr[o0 + jj + 1];
            p2n = *(const float4*)&g_P2[hr.x * D + j];
            ran = *(const float4*)&g_Ra[hr.y * D + j];
            g1n = *(const float4*)&g_G1[hr.x * D + j];
            rgn = *(const float4*)&g_Rg[hr.y * D + j];
        }
        float s = 0.f;
        s = fmaf(tanh_fast(p1.x + p2c.x + rac.x), av4.x, s);
        s = fmaf(tanh_fast(p1.y + p2c.y + rac.y), av4.y, s);
        s = fmaf(tanh_fast(p1.z + p2c.z + rac.z), av4.z, s);
        s = fmaf(tanh_fast(p1.w + p2c.w + rac.w), av4.w, s);
        s += __shfl_xor_sync(0xffffffffu, s, 1);
        s += __shfl_xor_sync(0xffffffffu, s, 2);
        float ev = __expf(s);

        ax = fmaf(ev, g1c.x + rgc.x, ax);   // g1 includes bg
        ay = fmaf(ev, g1c.y + rgc.y, ay);
        az = fmaf(ev, g1c.z + rgc.z, az);
        aw = fmaf(ev, g1c.w + rgc.w, aw);
        denom += ev;

        sax += rac.x; say += rac.y; saz += rac.z; saw += rac.w;
        sgx += rgc.x; sgy += rgc.y; sgz += rgc.z; sgw += rgc.w;

        p2c = p2n; rac = ran; g1c = g1n; rgc = rgn;
    }

    // ---- self edge: head = e, rel-feat = mean of Ra/Rg over incoming edges
    {
        float inv = (deg > 0) ? (1.0f / (float)deg) : 0.0f;
        float4 p2 = *(const float4*)&g_P2[e * D + j];
        float4 g1 = *(const float4*)&g_G1[e * D + j];
        float s = 0.f;
        s = fmaf(tanh_fast(p1.x + p2.x + sax * inv), av4.x, s);
        s = fmaf(tanh_fast(p1.y + p2.y + say * inv), av4.y, s);
        s = fmaf(tanh_fast(p1.z + p2.z + saz * inv), av4.z, s);
        s = fmaf(tanh_fast(p1.w + p2.w + saw * inv), av4.w, s);
        s += __shfl_xor_sync(0xffffffffu, s, 1);
        s += __shfl_xor_sync(0xffffffffu, s, 2);
        float ev = __expf(s);
        ax = fmaf(ev, g1.x + sgx * inv, ax);
        ay = fmaf(ev, g1.y + sgy * inv, ay);
        az = fmaf(ev, g1.z + sgz * inv, az);
        aw = fmaf(ev, g1.w + sgw * inv, aw);
        denom += ev;
    }

    float inv = 1.0f / denom;
    *(float4*)&out[e * D + j] = make_float4(ax * inv, ay * inv, az * inv, aw * inv);
}

// ---------------- launch: side stream = k_rel + CSR build (all hidden under
// k_ent); main stream = k_ent only; join before gather ----------------------
extern "C" void kernel_launch(void* const* d_in, const int* in_sizes, int n_in,
                              void* d_out, int out_size) {
    const float* emb_ent = (const float*)d_in[0];
    const float* emb_rel = (const float*)d_in[1];
    const int*   trip    = (const int*)d_in[2];
    const float* Wa      = (const float*)d_in[3];
    const float* ba      = (const float*)d_in[4];
    const float* av      = (const float*)d_in[5];
    const float* Wg      = (const float*)d_in[6];
    const float* bg      = (const float*)d_in[7];
    float* out = (float*)d_out;

    static cudaStream_t s2 = nullptr;
    static cudaEvent_t evF = nullptr, evJ = nullptr;
    if (s2 == nullptr) {
        cudaStreamCreateWithFlags(&s2, cudaStreamNonBlocking);
        cudaEventCreateWithFlags(&evF, cudaEventDisableTiming);
        cudaEventCreateWithFlags(&evJ, cudaEventDisableTiming);
        cudaFuncSetAttribute(k_ent, cudaFuncAttributeMaxDynamicSharedMemorySize, 49152);
    }

    // fork: rel GEMV + CSR build chain on side stream (~40us, hidden by k_ent)
    cudaEventRecord(evF, 0);
    cudaStreamWaitEvent(s2, evF, 0);
    k_rel<<<NRL, 128, 0, s2>>>(emb_rel, Wa, Wg);
    k_zero<<<(NE + 255) / 256, 256, 0, s2>>>();
    k_count<<<(NT + 255) / 256, 256, 0, s2>>>(trip);
    k_scanA<<<NBLK, 256, 0, s2>>>();
    k_scanB<<<1, 256, 0, s2>>>();
    k_scanC<<<NBLK, 256, 0, s2>>>();
    k_scatter<<<(NT + 255) / 256, 256, 0, s2>>>(trip);
    cudaEventRecord(evJ, s2);

    // main stream: entity GEMM only
    dim3 ent_grid((NE + 127) / 128, 3);
    k_ent<<<ent_grid, 256, 49152>>>(emb_ent, Wa, Wg, ba, bg);

    // join, then fused gather
    cudaStreamWaitEvent(0, evJ, 0);
    k_gather<<<(NE * 32 + 255) / 256, 256>>>(av, out);
}